// round 17
// baseline (speedup 1.0000x reference)
#include <cuda_runtime.h>
#include <cuda_fp16.h>
#include <cstdint>

#define B_    2048
#define N_    32
#define F_    64
#define E_    8
#define H_    128
#define NA_   4
#define NACT_ 16
#define KTOT  585      // 512 agg + 64 root + 8 mask-bias + 1 const-bias
#define KK16  40       // k16 blocks (K padded to 640)
#define KP2   320      // A2 rows (fp16x2 pairs along k)
#define ASTR  40       // A2 row stride (uint32); 40%32==8 -> conflict-free frags
#define U2STR 72       // u2 row stride (uint32); 72%32==8 -> conflict-free frags
#define NCH2  20       // 20 chunks x 2 k16-blocks

// __device__ scratch (no allocations allowed)
__device__ float g_Wcat[KTOT * H_];              // logical [k][h]
__device__ uint4 g_Bpack[KK16 * 4 * 2 * 32];     // [kk16][ng][h4][t] fp16 fragment-packed
__device__ uint32_t g_W1h[NA_ * H_ * 64];        // [a][k][hp] plain fp16x2 pairs

static __device__ __forceinline__ uint32_t pkh2(float lo, float hi) {
    __half2 h = __floats2half2_rn(lo, hi);
    return *reinterpret_cast<uint32_t*>(&h);
}
static __device__ __forceinline__ void mma_f16(float c[4], const uint32_t a[4],
                                               uint32_t b0, uint32_t b1) {
    asm volatile(
        "mma.sync.aligned.m16n8k16.row.col.f32.f16.f16.f32 "
        "{%0,%1,%2,%3},{%4,%5,%6,%7},{%8,%9},{%0,%1,%2,%3};"
        : "+f"(c[0]), "+f"(c[1]), "+f"(c[2]), "+f"(c[3])
        : "r"(a[0]), "r"(a[1]), "r"(a[2]), "r"(a[3]), "r"(b0), "r"(b1));
}

// ---------------------------------------------------------------------------
// Kernel A: fold We/be into Wrel/Wroot/brel -> g_Wcat[585][128]
// ---------------------------------------------------------------------------
__global__ void precompute_wcat(const float* __restrict__ We,
                                const float* __restrict__ be,
                                const float* __restrict__ Wrel,
                                const float* __restrict__ Wroot,
                                const float* __restrict__ brel) {
    __shared__ float vec[H_];
    const int r = blockIdx.x;
    const int h = threadIdx.x;
    const float* Bmat;
    float addv = 0.0f;
    if (r < 512) {
        int e = r >> 6, d = r & 63;
        vec[h] = We[d * H_ + h];
        Bmat = Wrel + e * H_ * H_;
    } else if (r < 576) {
        int d = r - 512;
        vec[h] = We[d * H_ + h];
        Bmat = Wroot;
    } else if (r < 584) {
        int e = r - 576;
        vec[h] = be[h];
        Bmat = Wrel + e * H_ * H_;
    } else {
        vec[h] = be[h];
        Bmat = Wroot;
        addv = brel[h];
    }
    __syncthreads();
    float a0 = 0.f, a1 = 0.f, a2 = 0.f, a3 = 0.f;
    #pragma unroll 8
    for (int t = 0; t < H_; t += 4) {
        a0 = fmaf(vec[t],     __ldg(Bmat + (t    ) * H_ + h), a0);
        a1 = fmaf(vec[t + 1], __ldg(Bmat + (t + 1) * H_ + h), a1);
        a2 = fmaf(vec[t + 2], __ldg(Bmat + (t + 2) * H_ + h), a2);
        a3 = fmaf(vec[t + 3], __ldg(Bmat + (t + 3) * H_ + h), a3);
    }
    g_Wcat[r * H_ + h] = addv + ((a0 + a1) + (a2 + a3));
}

// ---------------------------------------------------------------------------
// Kernel A2: pack fragments. Blocks 0..39: g_Wcat -> g_Bpack (zero-pad k>=585).
// Blocks 40..55: W1 -> g_W1h plain fp16x2 pairs ([a][k][hp]).
// ---------------------------------------------------------------------------
static __device__ __forceinline__ float wat(int k, int n) {
    return (k < KTOT) ? g_Wcat[k * H_ + n] : 0.0f;
}
__global__ void repack_b(const float* __restrict__ W1) {
    if (blockIdx.x < KK16) {
        int t   = threadIdx.x & 31;
        int hi4 = (threadIdx.x >> 5) & 1;
        int ng  = threadIdx.x >> 6;
        int kk  = blockIdx.x;
        int k0  = kk * 16 + (t & 3) * 2;
        int na  = ng * 32 + (hi4 * 2 + 0) * 8 + (t >> 2);
        int nb  = ng * 32 + (hi4 * 2 + 1) * 8 + (t >> 2);
        uint4 v;
        v.x = pkh2(wat(k0, na),     wat(k0 + 1, na));
        v.y = pkh2(wat(k0 + 8, na), wat(k0 + 9, na));
        v.z = pkh2(wat(k0, nb),     wat(k0 + 1, nb));
        v.w = pkh2(wat(k0 + 8, nb), wat(k0 + 9, nb));
        g_Bpack[((kk * 4 + ng) * 2 + hi4) * 32 + t] = v;
    } else {
        // W1 -> g_W1h: 65536 uint32 over 16 blocks x 256 threads x 16 each
        const float2* src = reinterpret_cast<const float2*>(W1);
        int base = (blockIdx.x - KK16) * 4096;
        #pragma unroll
        for (int p = 0; p < 16; ++p) {
            int idx = base + p * 256 + threadIdx.x;
            float2 v = __ldg(src + idx);
            g_W1h[idx] = pkh2(v.x, v.y);
        }
    }
}

// ---------------------------------------------------------------------------
// Kernel B: fully fused main kernel. ONE batch per CTA, 256 threads, fp16 mma
// RGCN + pool, then fused per-agent heads (W1 fp16 direct from L2).
// ---------------------------------------------------------------------------
struct SmemM {
    union AB {
        uint32_t A2[KP2][ASTR];      // 51200 B: fp16x2 pairs along k, [kp][j]
        float Cpart[2][32][132];     // 33792 B: k-split partials (epilogue)
    } ab;
    uint32_t u2[16][U2STR];          // 4608 B: u fp16x2 pairs along i, [ip][d]
    unsigned masks[256];             // [e*32 + j], bit i = A[b,e,i,j]
    float    cinv[256];
    float    pooled[H_];             // 512 B
    float    Z[NA_][H_];             // 2048 B
    int      cols[NA_];
};

__global__ __launch_bounds__(256, 3) void critic_main(
    const float* __restrict__ unary,    // [B,N,F]
    const int*   __restrict__ binary,   // [B,N,N,E]
    const float* __restrict__ actions,  // [NA,B,NACT]
    const float* __restrict__ b1,       // [NA,H]
    const float* __restrict__ W2,       // [NA,H,NACT]
    const float* __restrict__ b2,       // [NA,NACT]
    float* __restrict__ qout)           // [NA,B,1]
{
    extern __shared__ char raw[];
    SmemM& s = *reinterpret_cast<SmemM*>(raw);

    const int tid  = threadIdx.x;
    const int lane = tid & 31;
    const int w    = tid >> 5;          // 8 warps
    const int b    = blockIdx.x;        // one batch

    const float* up = unary + (size_t)b * (N_ * F_);

    // ---- u -> A2 root rows (pairs along d): A2[256+dp][j] = (u[j][2dp], u[j][2dp+1])
    {
        const float2* up2 = reinterpret_cast<const float2*>(up);
        #pragma unroll
        for (int p = 0; p < 4; ++p) {
            int idx = tid + p * 256;          // 1024 float2
            int j   = idx >> 5;
            int dp  = idx & 31;
            float2 v = up2[idx];
            s.ab.A2[256 + dp][j] = pkh2(v.x, v.y);
        }
    }
    // ---- u -> u2 (pairs along i): u2[ip][d] = (u[2ip][d], u[2ip+1][d])
    {
        #pragma unroll
        for (int p = 0; p < 4; ++p) {
            int idx = tid + p * 256;          // 1024 entries
            int ip  = idx >> 6;
            int d   = idx & 63;
            s.u2[ip][d] = pkh2(up[(2 * ip) * 64 + d], up[(2 * ip + 1) * 64 + d]);
        }
    }
    s.masks[tid] = 0u;
    __syncthreads();

    // ---- binary -> bitmasks: register-accumulate then 4 atomicOr ----
    {
        const int4* bb = reinterpret_cast<const int4*>(binary + (size_t)b * (N_ * N_ * E_));
        const int j  = (tid >> 1) & 31;
        const int e0 = (tid & 1) * 4;
        const int ib = tid >> 6;
        unsigned acc[4] = {0u, 0u, 0u, 0u};
        #pragma unroll
        for (int p = 0; p < 8; ++p) {
            int4 v = bb[tid + p * 256];
            unsigned bit = 1u << (ib + 4 * p);
            if (v.x) acc[0] |= bit;
            if (v.y) acc[1] |= bit;
            if (v.z) acc[2] |= bit;
            if (v.w) acc[3] |= bit;
        }
        #pragma unroll
        for (int sl = 0; sl < 4; ++sl)
            atomicOr(&s.masks[(e0 + sl) * 32 + j], acc[sl]);
    }
    __syncthreads();

    { int d = __popc(s.masks[tid]); s.cinv[tid] = d ? (1.0f / (float)d) : 0.0f; }
    __syncthreads();

    // ========================================================================
    // fp16 tensor-core aggregation: S_e[j][d] = sum_i adj_e[i,j] * u[i,d].
    // ========================================================================
    {
        const int gr = lane >> 2, gc = lane & 3;
        const int mt = w & 1;
        const int np = w >> 1;      // 0..3

        uint32_t uf[2][2][2];       // [nt2][kb][b0/b1]
        #pragma unroll
        for (int nt2 = 0; nt2 < 2; ++nt2) {
            int nt = np * 2 + nt2;
            #pragma unroll
            for (int kb = 0; kb < 2; ++kb) {
                uf[nt2][kb][0] = s.u2[kb * 8 + gc][nt * 8 + gr];
                uf[nt2][kb][1] = s.u2[kb * 8 + gc + 4][nt * 8 + gr];
            }
        }
        const int mcol = mt * 16 + gr;
        #pragma unroll
        for (int e = 0; e < E_; ++e) {
            const int mb = e * 32 + mt * 16 + gr;
            unsigned mr0 = s.masks[mb];
            unsigned mr1 = s.masks[mb + 8];
            float ci0 = s.cinv[mb];
            float ci1 = s.cinv[mb + 8];
            float acc0[4] = {0.f, 0.f, 0.f, 0.f};
            float acc1[4] = {0.f, 0.f, 0.f, 0.f};
            #pragma unroll
            for (int kb = 0; kb < 2; ++kb) {
                int bi = kb * 16 + 2 * gc;
                uint32_t ar[4];
                ar[0] = (((mr0 >> bi) & 1u) ? 0x3C00u : 0u)
                      | (((mr0 >> (bi + 1)) & 1u) ? 0x3C000000u : 0u);
                ar[1] = (((mr1 >> bi) & 1u) ? 0x3C00u : 0u)
                      | (((mr1 >> (bi + 1)) & 1u) ? 0x3C000000u : 0u);
                ar[2] = (((mr0 >> (bi + 8)) & 1u) ? 0x3C00u : 0u)
                      | (((mr0 >> (bi + 9)) & 1u) ? 0x3C000000u : 0u);
                ar[3] = (((mr1 >> (bi + 8)) & 1u) ? 0x3C00u : 0u)
                      | (((mr1 >> (bi + 9)) & 1u) ? 0x3C000000u : 0u);
                mma_f16(acc0, ar, uf[0][kb][0], uf[0][kb][1]);
                mma_f16(acc1, ar, uf[1][kb][0], uf[1][kb][1]);
            }
            {
                int rp = e * 32 + (np * 2 + 0) * 4 + gc;
                s.ab.A2[rp][mcol]     = pkh2(acc0[0] * ci0, acc0[1] * ci0);
                s.ab.A2[rp][mcol + 8] = pkh2(acc0[2] * ci1, acc0[3] * ci1);
            }
            {
                int rp = e * 32 + (np * 2 + 1) * 4 + gc;
                s.ab.A2[rp][mcol]     = pkh2(acc1[0] * ci0, acc1[1] * ci0);
                s.ab.A2[rp][mcol + 8] = pkh2(acc1[2] * ci1, acc1[3] * ci1);
            }
        }
    }
    // special rows: A rows 576..583 deg>0 pairs -> A2 288..291;
    // row 584 ones + 585 zero -> A2 292; rows 586..639 zero -> A2 293..319.
    {
        if (tid < 128) {
            int ep = tid >> 5, j2 = tid & 31;
            uint32_t v = (s.masks[(2 * ep) * 32 + j2] ? 0x3C00u : 0u)
                       | (s.masks[(2 * ep + 1) * 32 + j2] ? 0x3C000000u : 0u);
            s.ab.A2[288 + ep][j2] = v;
        }
        if (tid < 32) s.ab.A2[292][tid] = 0x3C00u;   // (1.0, 0.0)
        for (int r = tid; r < 27 * 32; r += 256)
            s.ab.A2[293 + (r >> 5)][r & 31] = 0u;
    }
    __syncthreads();   // A2 fully ready; no more barriers until epilogue

    // ========================================================================
    // Main GEMM: 8 warps = (ngp = w&3: n32 group, ks = w>>2: k16 parity).
    // ========================================================================
    const int ngp = w & 3;
    const int ks  = w >> 2;
    const int fc  = lane & 3;
    const int fr  = lane >> 2;

    float acc[2][4][4];
    #pragma unroll
    for (int mt2 = 0; mt2 < 2; ++mt2)
        #pragma unroll
        for (int nn = 0; nn < 4; ++nn)
            #pragma unroll
            for (int i = 0; i < 4; ++i) acc[mt2][nn][i] = 0.0f;

    const uint4* bptr = g_Bpack + (size_t)(((ks * 4 + ngp) * 2) * 32) + lane;
    uint4 nb0 = __ldg(bptr);
    uint4 nb1 = __ldg(bptr + 32);

    for (int ch = 0; ch < NCH2; ++ch) {
        const int kp0 = (ch * 2 + ks) * 8;
        uint32_t a0[4], a1[4];
        a0[0] = s.ab.A2[kp0 + fc][fr];
        a0[1] = s.ab.A2[kp0 + fc][fr + 8];
        a0[2] = s.ab.A2[kp0 + fc + 4][fr];
        a0[3] = s.ab.A2[kp0 + fc + 4][fr + 8];
        a1[0] = s.ab.A2[kp0 + fc][16 + fr];
        a1[1] = s.ab.A2[kp0 + fc][16 + fr + 8];
        a1[2] = s.ab.A2[kp0 + fc + 4][16 + fr];
        a1[3] = s.ab.A2[kp0 + fc + 4][16 + fr + 8];

        uint4 cb0 = nb0, cb1 = nb1;
        if (ch + 1 < NCH2) {
            bptr += 512;
            nb0 = __ldg(bptr);
            nb1 = __ldg(bptr + 32);
        }

        mma_f16(acc[0][0], a0, cb0.x, cb0.y);
        mma_f16(acc[0][1], a0, cb0.z, cb0.w);
        mma_f16(acc[0][2], a0, cb1.x, cb1.y);
        mma_f16(acc[0][3], a0, cb1.z, cb1.w);
        mma_f16(acc[1][0], a1, cb0.x, cb0.y);
        mma_f16(acc[1][1], a1, cb0.z, cb0.w);
        mma_f16(acc[1][2], a1, cb1.x, cb1.y);
        mma_f16(acc[1][3], a1, cb1.z, cb1.w);
    }

    // ---- store k-split partials (A2 region dead now) ----
    __syncthreads();
    {
        float* Cp = &s.ab.Cpart[ks][0][0];
        #pragma unroll
        for (int mt2 = 0; mt2 < 2; ++mt2) {
            const int row = mt2 * 16 + fr;
            #pragma unroll
            for (int nn = 0; nn < 4; ++nn) {
                const int col = ngp * 32 + nn * 8 + 2 * fc;
                Cp[row * 132 + col]           = acc[mt2][nn][0];
                Cp[row * 132 + col + 1]       = acc[mt2][nn][1];
                Cp[(row + 8) * 132 + col]     = acc[mt2][nn][2];
                Cp[(row + 8) * 132 + col + 1] = acc[mt2][nn][3];
            }
        }
    }
    __syncthreads();

    // ---- merge partials + relu + max-pool (tid<128); argmax (tid 128..131) ----
    if (tid < 128) {
        const int h = tid;
        float mx = -3.0e38f;
        #pragma unroll 4
        for (int j = 0; j < N_; ++j) {
            float v = s.ab.Cpart[0][j][h] + s.ab.Cpart[1][j][h];
            mx = fmaxf(mx, v);
        }
        s.pooled[h] = fmaxf(mx, 0.0f);
    } else if (tid < 128 + NA_) {
        const int a = tid - 128;
        const float* ap = actions + ((size_t)a * B_ + b) * NACT_;
        float best = ap[0]; int col = 0;
        #pragma unroll
        for (int k = 1; k < NACT_; ++k) {
            float v = ap[k];
            if (v > best) { best = v; col = k; }
        }
        s.cols[a] = col;
    }
    __syncthreads();

    // ---- fused heads: z = leaky(pooled @ W1[a] + b1[a]), W1 fp16 from L2 ----
    {
        const int a  = tid >> 6;        // agent
        const int hp = tid & 63;        // h pair
        const uint32_t* w1p = g_W1h + ((size_t)a * H_) * 64 + hp;
        float z0 = __ldg(b1 + a * H_ + 2 * hp);
        float z1 = __ldg(b1 + a * H_ + 2 * hp + 1);
        #pragma unroll 8
        for (int k = 0; k < H_; ++k) {
            uint32_t wb = __ldg(w1p + k * 64);
            __half2 wh = *reinterpret_cast<__half2*>(&wb);
            float2 wf = __half22float2(wh);
            float p = s.pooled[k];      // smem broadcast
            z0 = fmaf(p, wf.x, z0);
            z1 = fmaf(p, wf.y, z1);
        }
        s.Z[a][2 * hp]     = (z0 > 0.f) ? z0 : 0.01f * z0;
        s.Z[a][2 * hp + 1] = (z1 > 0.f) ? z1 : 0.01f * z1;
    }
    __syncthreads();

    // ---- q = z @ W2[:, col] + b2 (16 threads) ----
    if (tid < 16) {
        const int a  = tid >> 2;
        const int qt = tid & 3;
        const int col = s.cols[a];
        const float* w2p = W2 + (size_t)a * H_ * NACT_ + col;
        float part = 0.f;
        #pragma unroll 8
        for (int i = 0; i < 32; ++i) {
            int h = i * 4 + qt;
            part = fmaf(s.Z[a][h], __ldg(w2p + h * NACT_), part);
        }
        part += __shfl_xor_sync(0x0000ffffu, part, 1);
        part += __shfl_xor_sync(0x0000ffffu, part, 2);
        if (qt == 0)
            qout[(size_t)a * B_ + b] = part + __ldg(b2 + a * NACT_ + col);
    }
}

// ---------------------------------------------------------------------------
extern "C" void kernel_launch(void* const* d_in, const int* in_sizes, int n_in,
                              void* d_out, int out_size) {
    const float* unary   = (const float*)d_in[0];
    const int*   binary  = (const int*)  d_in[1];
    const float* actions = (const float*)d_in[2];
    const float* We      = (const float*)d_in[3];
    const float* be      = (const float*)d_in[4];
    const float* Wrel    = (const float*)d_in[5];
    const float* Wroot   = (const float*)d_in[6];
    const float* brel    = (const float*)d_in[7];
    const float* W1      = (const float*)d_in[8];
    const float* b1      = (const float*)d_in[9];
    const float* W2      = (const float*)d_in[10];
    const float* b2      = (const float*)d_in[11];
    float* qout = (float*)d_out;

    cudaFuncSetAttribute(critic_main, cudaFuncAttributeMaxDynamicSharedMemorySize,
                         (int)sizeof(SmemM));

    precompute_wcat<<<KTOT, H_>>>(We, be, Wrel, Wroot, brel);
    repack_b<<<KK16 + 16, 256>>>(W1);
    critic_main<<<B_, 256, sizeof(SmemM)>>>(unary, binary, actions, b1, W2, b2, qout);
}